// round 5
// baseline (speedup 1.0000x reference)
#include <cuda_runtime.h>
#include <cstdint>

#define BB 16
#define DD 512
#define TT 4096

// recurrence: 16 clusters (=batches) x 8 CTAs (=64-col slices) x 128 threads
#define JPC 64
#define WT_STRIDE 516                       // padded col stride (conflict-free LDS.128)
#define WT_FLOATS (JPC * WT_STRIDE)         // 33024
#define FEAT_FLOATS (2 * DD)                // double-buffered feat
#define RED_FLOATS 64
#define SMEM_REC_BYTES ((WT_FLOATS + FEAT_FLOATS + RED_FLOATS) * 4)

// resbuf[b][i][t]  (128 MB) static scratch
__device__ float g_resbuf[(size_t)BB * DD * TT];

__device__ __forceinline__ uint32_t smem_u32(const void* p) {
    uint32_t a;
    asm("{ .reg .u64 t; cvta.to.shared.u64 t, %1; cvt.u32.u64 %0, t; }" : "=r"(a) : "l"(p));
    return a;
}
__device__ __forceinline__ void st_cluster_f32(uint32_t addr, uint32_t rank, float v) {
    asm volatile("{ .reg .u32 r; mapa.shared::cluster.u32 r, %0, %1; st.shared::cluster.f32 [r], %2; }"
                 :: "r"(addr), "r"(rank), "f"(v) : "memory");
}
__device__ __forceinline__ void cluster_sync_() {
    asm volatile("barrier.cluster.arrive.aligned;" ::: "memory");
    asm volatile("barrier.cluster.wait.aligned;" ::: "memory");
}

// ============================================================================
// Recurrence, ordering "C" (identified bit-exact in round 4):
// per element: h0 = fma-chain over k=0..255 (single fp32 acc, ascending k),
//              h1 = fma-chain over k=256..511, s = h0 + h1,
//              v = clip(4*(s + x)).
// Thread (tid&63)=column, (tid>>6)=half. The two 256-chains run in parallel
// threads -> per-step critical path = 256 dependent FMAs = 1024 cyc.
// ============================================================================
__global__ void __cluster_dims__(8, 1, 1) __launch_bounds__(128, 1)
rec_kernel(const float* __restrict__ x, const float* __restrict__ W) {
    extern __shared__ float sm[];
    float* Wt    = sm;                           // [64][516]: Wt[col][k]
    float* feats = sm + WT_FLOATS;               // [2][512]
    float* red   = sm + WT_FLOATS + FEAT_FLOATS; // [64]

    const int tid  = threadIdx.x;
    const int rank = blockIdx.x & 7;
    const int b    = blockIdx.x >> 3;
    const int col  = tid & 63;
    const int h    = tid >> 6;        // 0 or 1 (which 256-half)
    const int j0   = rank * JPC;
    const int gj   = j0 + col;

    // Load W slice transposed: Wt[col][k] = W[k][j0+col]  (one-time)
    for (int idx = tid; idx < DD * JPC; idx += 128) {
        int k  = idx >> 6;
        int jl = idx & 63;
        Wt[jl * WT_STRIDE + k] = W[(size_t)k * DD + j0 + jl];
    }
    for (int idx = tid; idx < FEAT_FLOATS; idx += 128) feats[idx] = 0.f;

    const uint32_t feats_u32 = smem_u32(feats);
    const float4* __restrict__ wr4 =
        (const float4*)(Wt + col * WT_STRIDE + h * 256);
    const float* __restrict__ xp = x + ((size_t)b * DD + gj) * TT;
    float* __restrict__ rp = g_resbuf + ((size_t)b * DD + gj) * TT;

    __syncthreads();
    cluster_sync_();

    for (int t = 0; t < TT; t++) {
        const int cur = t & 1;
        const int nxt = cur ^ 1;

        // x value (only half-0 threads need it) -- issued before the chain
        float xv = 0.f;
        if (h == 0) xv = __ldg(xp + t);

        // 256-long single-accumulator fma chain, ascending k within the half
        const float4* __restrict__ f4 =
            (const float4*)(feats + cur * DD) + h * 64;
        float a = 0.f;
#pragma unroll
        for (int k4 = 0; k4 < 64; k4++) {
            const float4 f = f4[k4];
            const float4 w = wr4[k4];
            a = fmaf(f.x, w.x, a);
            a = fmaf(f.y, w.y, a);
            a = fmaf(f.z, w.z, a);
            a = fmaf(f.w, w.w, a);
        }

        if (h == 1) red[col] = a;
        __syncthreads();

        if (h == 0) {
            const float s = a + red[col];            // h0 + h1 (exact order)
            const float v = fminf(1.f, fmaxf(-1.f, 4.f * (s + xv)));
            rp[t] = v;
            // broadcast new feat value to all 8 cluster ranks
            const uint32_t dst = feats_u32 + (uint32_t)(nxt * DD + gj) * 4u;
#pragma unroll
            for (int rr = 0; rr < 8; rr++) st_cluster_f32(dst, (uint32_t)rr, v);
        }
        cluster_sync_();
    }
}

// ============================================================================
// Projection: out[b][o][t] = sum_i lin_w[o][i] * resbuf[b][i][t] + lin_b[o]
// fp32 FMA GEMM, 128x128 tile, 8x8 microtile. (Output-only: fp32 reorder
// noise ~1e-6 rel, no feedback.)
// ============================================================================
__global__ void __launch_bounds__(256) proj_kernel(
    const float* __restrict__ lin_w, const float* __restrict__ lin_b,
    float* __restrict__ out) {

    const float* rb = g_resbuf;
    const int b  = blockIdx.z;
    const int o0 = blockIdx.y * 128;
    const int t0 = blockIdx.x * 128;

    __shared__ float As[8][128];
    __shared__ float Bs[8][128];

    const int tid = threadIdx.x;
    const int tx  = tid & 15;
    const int ty  = tid >> 4;

    float acc[8][8];
#pragma unroll
    for (int r = 0; r < 8; r++)
#pragma unroll
        for (int c = 0; c < 8; c++) acc[r][c] = 0.f;

    const int lo   = tid >> 1;
    const int half = (tid & 1) * 4;
    const int brow = tid >> 5;
    const int bc4  = (tid & 31) * 4;

    for (int k0 = 0; k0 < DD; k0 += 8) {
        float4 av = *(const float4*)&lin_w[(size_t)(o0 + lo) * DD + k0 + half];
        float4 bv = *(const float4*)&rb[((size_t)b * DD + k0 + brow) * TT + t0 + bc4];
        __syncthreads();
        As[half + 0][lo] = av.x; As[half + 1][lo] = av.y;
        As[half + 2][lo] = av.z; As[half + 3][lo] = av.w;
        *(float4*)&Bs[brow][bc4] = bv;
        __syncthreads();

#pragma unroll
        for (int ii = 0; ii < 8; ii++) {
            float4 a0 = *(const float4*)&As[ii][ty * 8];
            float4 a1 = *(const float4*)&As[ii][ty * 8 + 4];
            float4 b0 = *(const float4*)&Bs[ii][tx * 8];
            float4 b1 = *(const float4*)&Bs[ii][tx * 8 + 4];
            float a[8]  = {a0.x, a0.y, a0.z, a0.w, a1.x, a1.y, a1.z, a1.w};
            float bb[8] = {b0.x, b0.y, b0.z, b0.w, b1.x, b1.y, b1.z, b1.w};
#pragma unroll
            for (int r = 0; r < 8; r++)
#pragma unroll
                for (int c = 0; c < 8; c++)
                    acc[r][c] = fmaf(a[r], bb[c], acc[r][c]);
        }
    }

#pragma unroll
    for (int r = 0; r < 8; r++) {
        const int o = o0 + ty * 8 + r;
        const float bias = lin_b[o];
        float4 v0, v1;
        v0.x = acc[r][0] + bias; v0.y = acc[r][1] + bias;
        v0.z = acc[r][2] + bias; v0.w = acc[r][3] + bias;
        v1.x = acc[r][4] + bias; v1.y = acc[r][5] + bias;
        v1.z = acc[r][6] + bias; v1.w = acc[r][7] + bias;
        float* op = &out[((size_t)b * DD + o) * TT + t0 + tx * 8];
        *(float4*)op       = v0;
        *(float4*)(op + 4) = v1;
    }
}

extern "C" void kernel_launch(void* const* d_in, const int* in_sizes, int n_in,
                              void* d_out, int out_size) {
    const float* x     = (const float*)d_in[0];
    const float* W     = (const float*)d_in[1];
    const float* lin_w = (const float*)d_in[2];
    const float* lin_b = (const float*)d_in[3];
    float* out = (float*)d_out;

    cudaFuncSetAttribute(rec_kernel,
                         cudaFuncAttributeMaxDynamicSharedMemorySize,
                         SMEM_REC_BYTES);
    rec_kernel<<<dim3(BB * 8), 128, SMEM_REC_BYTES>>>(x, W);
    proj_kernel<<<dim3(TT / 128, DD / 128, BB), 256>>>(lin_w, lin_b, out);
}

// round 6
// speedup vs baseline: 1.3519x; 1.3519x over previous
#include <cuda_runtime.h>
#include <cstdint>

#define BB 16
#define DD 512
#define TT 4096

// recurrence: 16 clusters (=batches) x 8 CTAs (=64-col slices) x 128 threads
#define JPC 64
#define WT_STRIDE 516                       // padded col stride (conflict-free LDS.128)
#define WT_FLOATS (JPC * WT_STRIDE)         // 33024
#define FEAT_FLOATS (2 * DD)                // double-buffered feat
#define RED_FLOATS 64
#define SMEM_REC_BYTES ((WT_FLOATS + FEAT_FLOATS + RED_FLOATS) * 4)

// resbuf[b][i][t]  (128 MB) static scratch
__device__ float g_resbuf[(size_t)BB * DD * TT];

__device__ __forceinline__ uint32_t smem_u32(const void* p) {
    uint32_t a;
    asm("{ .reg .u64 t; cvta.to.shared.u64 t, %1; cvt.u32.u64 %0, t; }" : "=r"(a) : "l"(p));
    return a;
}
__device__ __forceinline__ void st_cluster_f32(uint32_t addr, uint32_t rank, float v) {
    asm volatile("{ .reg .u32 r; mapa.shared::cluster.u32 r, %0, %1; st.shared::cluster.f32 [r], %2; }"
                 :: "r"(addr), "r"(rank), "f"(v) : "memory");
}
__device__ __forceinline__ void cluster_sync_() {
    asm volatile("barrier.cluster.arrive.aligned;" ::: "memory");
    asm volatile("barrier.cluster.wait.aligned;" ::: "memory");
}

// ============================================================================
// Recurrence, ordering "C" (bit-exact, verified round 5):
// per element: h0 = fma-chain k=0..255 (single fp32 acc, ascending k),
//              h1 = fma-chain k=256..511, s = h0 + h1, v = clip(4*(s+x)).
//
// Perf structure vs round 5:
//  - W for EVEN 4-k groups pinned in 128 registers per thread (loaded once),
//    ODD groups read from SMEM -> crossbar ~768 cyc/step < 1024-cyc chain.
//  - full unroll but only ~90 free regs -> ptxas lookahead bounded, no spills.
// ============================================================================
__global__ void __cluster_dims__(8, 1, 1) __launch_bounds__(128, 1)
rec_kernel(const float* __restrict__ x, const float* __restrict__ W) {
    extern __shared__ float sm[];
    float* Wt    = sm;                           // [64][516]: Wt[col][k]
    float* feats = sm + WT_FLOATS;               // [2][512]
    float* red   = sm + WT_FLOATS + FEAT_FLOATS; // [64]

    const int tid  = threadIdx.x;
    const int rank = blockIdx.x & 7;
    const int b    = blockIdx.x >> 3;
    const int col  = tid & 63;
    const int h    = tid >> 6;        // 0 or 1 (which 256-half)
    const int j0   = rank * JPC;
    const int gj   = j0 + col;

    // SMEM W slice transposed: Wt[col][k] = W[k][j0+col]  (one-time)
    for (int idx = tid; idx < DD * JPC; idx += 128) {
        int k  = idx >> 6;
        int jl = idx & 63;
        Wt[jl * WT_STRIDE + k] = W[(size_t)k * DD + j0 + jl];
    }
    for (int idx = tid; idx < FEAT_FLOATS; idx += 128) feats[idx] = 0.f;

    // Register-pinned W: even 4-k groups of this thread's half.
    // group g (0..63) covers k = h*256 + 4g; even g -> wreg[(g/2)*4 + j].
    float wreg[128];
#pragma unroll
    for (int g2 = 0; g2 < 32; g2++) {
#pragma unroll
        for (int j = 0; j < 4; j++)
            wreg[g2 * 4 + j] = W[(size_t)(h * 256 + g2 * 8 + j) * DD + gj];
    }

    const uint32_t feats_u32 = smem_u32(feats);
    const float4* __restrict__ wr4 =
        (const float4*)(Wt + col * WT_STRIDE + h * 256);   // [64] groups
    const float* __restrict__ xp = x + ((size_t)b * DD + gj) * TT;
    float* __restrict__ rp = g_resbuf + ((size_t)b * DD + gj) * TT;

    __syncthreads();
    cluster_sync_();

    for (int t = 0; t < TT; t++) {
        const int cur = t & 1;
        const int nxt = cur ^ 1;

        float xv = 0.f;
        if (h == 0) xv = __ldg(xp + t);   // consumed ~1000 cyc later

        // 256-long single-accumulator fma chain, ascending k.
        // Even groups use registers, odd groups use SMEM (order unchanged).
        const float4* __restrict__ f4 =
            (const float4*)(feats + cur * DD) + h * 64;
        float a = 0.f;
#pragma unroll
        for (int g2 = 0; g2 < 32; g2++) {
            const float4 f0 = f4[2 * g2];              // even group: W in regs
            a = fmaf(f0.x, wreg[4 * g2 + 0], a);
            a = fmaf(f0.y, wreg[4 * g2 + 1], a);
            a = fmaf(f0.z, wreg[4 * g2 + 2], a);
            a = fmaf(f0.w, wreg[4 * g2 + 3], a);
            const float4 f1 = f4[2 * g2 + 1];          // odd group: W in SMEM
            const float4 w1 = wr4[2 * g2 + 1];
            a = fmaf(f1.x, w1.x, a);
            a = fmaf(f1.y, w1.y, a);
            a = fmaf(f1.z, w1.z, a);
            a = fmaf(f1.w, w1.w, a);
        }

        if (h == 1) red[col] = a;
        __syncthreads();

        if (h == 0) {
            const float s = a + red[col];            // h0 + h1 (exact order)
            const float v = fminf(1.f, fmaxf(-1.f, 4.f * (s + xv)));
            rp[t] = v;
            const uint32_t dst = feats_u32 + (uint32_t)(nxt * DD + gj) * 4u;
#pragma unroll
            for (int rr = 0; rr < 8; rr++) st_cluster_f32(dst, (uint32_t)rr, v);
        }
        cluster_sync_();
    }
}

// ============================================================================
// Projection: out[b][o][t] = sum_i lin_w[o][i] * resbuf[b][i][t] + lin_b[o]
// ============================================================================
__global__ void __launch_bounds__(256) proj_kernel(
    const float* __restrict__ lin_w, const float* __restrict__ lin_b,
    float* __restrict__ out) {

    const float* rb = g_resbuf;
    const int b  = blockIdx.z;
    const int o0 = blockIdx.y * 128;
    const int t0 = blockIdx.x * 128;

    __shared__ float As[8][128];
    __shared__ float Bs[8][128];

    const int tid = threadIdx.x;
    const int tx  = tid & 15;
    const int ty  = tid >> 4;

    float acc[8][8];
#pragma unroll
    for (int r = 0; r < 8; r++)
#pragma unroll
        for (int c = 0; c < 8; c++) acc[r][c] = 0.f;

    const int lo   = tid >> 1;
    const int half = (tid & 1) * 4;
    const int brow = tid >> 5;
    const int bc4  = (tid & 31) * 4;

    for (int k0 = 0; k0 < DD; k0 += 8) {
        float4 av = *(const float4*)&lin_w[(size_t)(o0 + lo) * DD + k0 + half];
        float4 bv = *(const float4*)&rb[((size_t)b * DD + k0 + brow) * TT + t0 + bc4];
        __syncthreads();
        As[half + 0][lo] = av.x; As[half + 1][lo] = av.y;
        As[half + 2][lo] = av.z; As[half + 3][lo] = av.w;
        *(float4*)&Bs[brow][bc4] = bv;
        __syncthreads();

#pragma unroll
        for (int ii = 0; ii < 8; ii++) {
            float4 a0 = *(const float4*)&As[ii][ty * 8];
            float4 a1 = *(const float4*)&As[ii][ty * 8 + 4];
            float4 b0 = *(const float4*)&Bs[ii][tx * 8];
            float4 b1 = *(const float4*)&Bs[ii][tx * 8 + 4];
            float a[8]  = {a0.x, a0.y, a0.z, a0.w, a1.x, a1.y, a1.z, a1.w};
            float bb[8] = {b0.x, b0.y, b0.z, b0.w, b1.x, b1.y, b1.z, b1.w};
#pragma unroll
            for (int r = 0; r < 8; r++)
#pragma unroll
                for (int c = 0; c < 8; c++)
                    acc[r][c] = fmaf(a[r], bb[c], acc[r][c]);
        }
    }

#pragma unroll
    for (int r = 0; r < 8; r++) {
        const int o = o0 + ty * 8 + r;
        const float bias = lin_b[o];
        float4 v0, v1;
        v0.x = acc[r][0] + bias; v0.y = acc[r][1] + bias;
        v0.z = acc[r][2] + bias; v0.w = acc[r][3] + bias;
        v1.x = acc[r][4] + bias; v1.y = acc[r][5] + bias;
        v1.z = acc[r][6] + bias; v1.w = acc[r][7] + bias;
        float* op = &out[((size_t)b * DD + o) * TT + t0 + tx * 8];
        *(float4*)op       = v0;
        *(float4*)(op + 4) = v1;
    }
}

extern "C" void kernel_launch(void* const* d_in, const int* in_sizes, int n_in,
                              void* d_out, int out_size) {
    const float* x     = (const float*)d_in[0];
    const float* W     = (const float*)d_in[1];
    const float* lin_w = (const float*)d_in[2];
    const float* lin_b = (const float*)d_in[3];
    float* out = (float*)d_out;

    cudaFuncSetAttribute(rec_kernel,
                         cudaFuncAttributeMaxDynamicSharedMemorySize,
                         SMEM_REC_BYTES);
    rec_kernel<<<dim3(BB * 8), 128, SMEM_REC_BYTES>>>(x, W);
    proj_kernel<<<dim3(TT / 128, DD / 128, BB), 256>>>(lin_w, lin_b, out);
}